// round 4
// baseline (speedup 1.0000x reference)
#include <cuda_runtime.h>

#define NTOK 8192
#define DIM 128
#define ODIM 128
#define OT 4
#define TOKPT 4
#define THREADS 256

typedef unsigned long long u64;

__device__ __forceinline__ float2 ffma2(float2 a, float2 b, float2 c) {
    float2 d;
    asm("fma.rn.f32x2 %0, %1, %2, %3;"
        : "=l"(reinterpret_cast<u64&>(d))
        : "l"(reinterpret_cast<u64 const&>(a)),
          "l"(reinterpret_cast<u64 const&>(b)),
          "l"(reinterpret_cast<u64 const&>(c)));
    return d;
}
__device__ __forceinline__ float2 fmul2(float2 a, float2 b) {
    float2 d;
    asm("mul.rn.f32x2 %0, %1, %2;"
        : "=l"(reinterpret_cast<u64&>(d))
        : "l"(reinterpret_cast<u64 const&>(a)),
          "l"(reinterpret_cast<u64 const&>(b)));
    return d;
}
__device__ __forceinline__ float2 fadd2(float2 a, float2 b) {
    float2 d;
    asm("add.rn.f32x2 %0, %1, %2;"
        : "=l"(reinterpret_cast<u64&>(d))
        : "l"(reinterpret_cast<u64 const&>(a)),
          "l"(reinterpret_cast<u64 const&>(b)));
    return d;
}
__device__ __forceinline__ float ex2f(float a) {
    float r; asm("ex2.approx.ftz.f32 %0, %1;" : "=f"(r) : "f"(a)); return r;
}

// Math:
//   s = softplus(scale)+0.1, z=(xn-t)/s, H=0.5*log2(e)=0.72134752
//   m = H - H*(xn-t)^2/s^2 = ffma2((xn+T)^2, a, H)   [T=-t, a=-H/s^2]
//   wavelet term = CP * m * 2^m,  CP = -(C*e^{-1/2}/H)*ww = -0.7292728*ww
//   base GEMM in xn-domain: base_o = sv*(sum_d xn_d*W'_od - K1_o) + mu*K2_o
//     W' = bw/gamma, K1_o = sum beta_d W'_od, K2_o = sum bw_od, sv = sqrt(var+eps)
__global__ __launch_bounds__(THREADS, 2)
void wavekan_fused(const float* __restrict__ x,
                   const float* __restrict__ scale,
                   const float* __restrict__ trans,
                   const float* __restrict__ ww,
                   const float* __restrict__ bw,
                   const float* __restrict__ gamma,
                   const float* __restrict__ beta,
                   float* __restrict__ out) {
    __shared__ float4 sT [OT][DIM / 4];
    __shared__ float4 sA [OT][DIM / 4];
    __shared__ float4 sCP[OT][DIM / 4];
    __shared__ float4 sW [OT][DIM / 4];   // W' = bw/gamma
    __shared__ float4 sG [DIM / 4];
    __shared__ float4 sBt[DIM / 4];
    __shared__ float  sK1[OT], sK2[OT];

    const int o0 = blockIdx.y * OT;
    const int tid = threadIdx.x;
    const float H = 0.72134752f;

    // ---- fold params for this o-tile into smem ----
    #pragma unroll
    for (int k = 0; k < (OT * DIM) / THREADS; k++) {
        int i = tid + k * THREADS;
        int gi = o0 * DIM + i;
        int d = i & (DIM - 1);
        float sc = scale[gi];
        float sp = (sc > 20.0f) ? sc : log1pf(expf(sc));
        float s = sp + 0.1f;
        ((float*)sT)[i]  = -trans[gi];
        ((float*)sA)[i]  = -H / (s * s);
        ((float*)sCP)[i] = -0.7292728f * ww[gi];
        ((float*)sW)[i]  = bw[gi] / gamma[d];
    }
    if (tid < DIM / 4) {
        sG[tid]  = ((const float4*)gamma)[tid];
        sBt[tid] = ((const float4*)beta)[tid];
    }

    // ---- per-thread LayerNorm stats for TOKPT tokens ----
    const float* xbase = x + ((size_t)blockIdx.x * (THREADS * TOKPT) + tid) * DIM;
    const float4* x4 = (const float4*)xbase;   // token j at float4-offset j*THREADS*32
    float nmu[TOKPT], rstv[TOKPT], svv[TOKPT];
    #pragma unroll
    for (int j = 0; j < TOKPT; j++) {
        float sm = 0.0f, sq = 0.0f;
        #pragma unroll 4
        for (int dc = 0; dc < DIM / 4; dc++) {
            float4 v = x4[j * (THREADS * DIM / 4) + dc];
            sm += (v.x + v.y) + (v.z + v.w);
            sq += (v.x * v.x + v.y * v.y) + (v.z * v.z + v.w * v.w);
        }
        float mu = sm * (1.0f / DIM);
        float var = fmaf(-mu, mu, sq * (1.0f / DIM)) + 1e-5f;
        float rst = rsqrtf(var);
        nmu[j] = -mu;
        rstv[j] = rst;
        svv[j] = var * rst;     // sqrt(var+eps)
    }
    __syncthreads();

    // ---- K1, K2 per o (one warp per o) ----
    if (tid < OT * 32) {
        int o = tid >> 5, lane = tid & 31;
        float4 w4 = sW[o][lane];
        float4 b4 = sBt[lane];
        float4 g4 = sG[lane];
        float k1 = (w4.x * b4.x + w4.y * b4.y) + (w4.z * b4.z + w4.w * b4.w);
        float k2 = (w4.x * g4.x + w4.y * g4.y) + (w4.z * g4.z + w4.w * g4.w);
        #pragma unroll
        for (int off = 16; off; off >>= 1) {
            k1 += __shfl_xor_sync(0xffffffffu, k1, off);
            k2 += __shfl_xor_sync(0xffffffffu, k2, off);
        }
        if (lane == 0) { sK1[o] = k1; sK2[o] = k2; }
    }
    __syncthreads();

    const float2 H2 = make_float2(H, H);
    float2 accw[OT][TOKPT], accb[OT][TOKPT];
    #pragma unroll
    for (int o = 0; o < OT; o++)
        #pragma unroll
        for (int j = 0; j < TOKPT; j++) {
            accw[o][j] = make_float2(0.0f, 0.0f);
            accb[o][j] = make_float2(0.0f, 0.0f);
        }

    for (int dc = 0; dc < DIM / 4; dc++) {
        float4 g4 = sG[dc];
        float4 b4 = sBt[dc];
        float2 xn[TOKPT][2];
        #pragma unroll
        for (int j = 0; j < TOKPT; j++) {
            float4 xv = x4[j * (THREADS * DIM / 4) + dc];
            float2 r2 = make_float2(rstv[j], rstv[j]);
            float2 nm = make_float2(nmu[j], nmu[j]);
            float2 rg_lo = fmul2(make_float2(g4.x, g4.y), r2);
            float2 rg_hi = fmul2(make_float2(g4.z, g4.w), r2);
            float2 c_lo = ffma2(rg_lo, nm, make_float2(b4.x, b4.y));
            float2 c_hi = ffma2(rg_hi, nm, make_float2(b4.z, b4.w));
            xn[j][0] = ffma2(make_float2(xv.x, xv.y), rg_lo, c_lo);
            xn[j][1] = ffma2(make_float2(xv.z, xv.w), rg_hi, c_hi);
        }

        #pragma unroll
        for (int o = 0; o < OT; o++) {
            float4 T4 = sT [o][dc];
            float4 A4 = sA [o][dc];
            float4 P4 = sCP[o][dc];
            float4 W4 = sW [o][dc];
            float2 Tlo = make_float2(T4.x, T4.y), Thi = make_float2(T4.z, T4.w);
            float2 Alo = make_float2(A4.x, A4.y), Ahi = make_float2(A4.z, A4.w);
            float2 Plo = make_float2(P4.x, P4.y), Phi = make_float2(P4.z, P4.w);
            float2 Wlo = make_float2(W4.x, W4.y), Whi = make_float2(W4.z, W4.w);
            #pragma unroll
            for (int j = 0; j < TOKPT; j++) {
                {
                    float2 y = fadd2(xn[j][0], Tlo);
                    float2 q = fmul2(y, y);
                    float2 m = ffma2(q, Alo, H2);
                    float2 e = make_float2(ex2f(m.x), ex2f(m.y));
                    float2 t = fmul2(m, e);
                    accw[o][j] = ffma2(t, Plo, accw[o][j]);
                }
                {
                    float2 y = fadd2(xn[j][1], Thi);
                    float2 q = fmul2(y, y);
                    float2 m = ffma2(q, Ahi, H2);
                    float2 e = make_float2(ex2f(m.x), ex2f(m.y));
                    float2 t = fmul2(m, e);
                    accw[o][j] = ffma2(t, Phi, accw[o][j]);
                }
                accb[o][j] = ffma2(xn[j][0], Wlo, accb[o][j]);
                accb[o][j] = ffma2(xn[j][1], Whi, accb[o][j]);
            }
        }
    }

    // ---- epilogue: out = wavelet + silu(base) ----
    float* obase = out + ((size_t)blockIdx.x * (THREADS * TOKPT) + tid) * ODIM + o0;
    #pragma unroll
    for (int j = 0; j < TOKPT; j++) {
        float4 res;
        float* rp = (float*)&res;
        float muj = -nmu[j];
        #pragma unroll
        for (int o = 0; o < OT; o++) {
            float ac = accb[o][j].x + accb[o][j].y;
            float b = fmaf(svv[j], ac - sK1[o], muj * sK2[o]);
            float t = ex2f(-1.44269504f * b);
            float sig = __frcp_rn(1.0f + t);
            rp[o] = fmaf(b, sig, accw[o][j].x + accw[o][j].y);
        }
        ((float4*)(obase + (size_t)j * THREADS * ODIM))[0] = res;
    }
}

extern "C" void kernel_launch(void* const* d_in, const int* in_sizes, int n_in,
                              void* d_out, int out_size) {
    const float* x     = (const float*)d_in[0];
    const float* scale = (const float*)d_in[1];
    const float* trans = (const float*)d_in[2];
    const float* ww    = (const float*)d_in[3];
    const float* bw    = (const float*)d_in[4];
    const float* gamma = (const float*)d_in[5];
    const float* beta  = (const float*)d_in[6];
    float* out = (float*)d_out;

    dim3 grid(NTOK / (THREADS * TOKPT), ODIM / OT);
    wavekan_fused<<<grid, THREADS>>>(x, scale, trans, ww, bw, gamma, beta, out);
}

// round 5
// speedup vs baseline: 1.0528x; 1.0528x over previous
#include <cuda_runtime.h>

#define NTOK 8192
#define DIM 128
#define ODIM 128
#define TOKB 64          // tokens per block
#define THREADS 256      // 8 warps, each owns one o

typedef unsigned long long u64;

__device__ float g_xnorm[NTOK * DIM];
__device__ float2 g_musv[NTOK];

__device__ __forceinline__ float2 ffma2(float2 a, float2 b, float2 c) {
    float2 d;
    asm("fma.rn.f32x2 %0, %1, %2, %3;"
        : "=l"(reinterpret_cast<u64&>(d))
        : "l"(reinterpret_cast<u64 const&>(a)),
          "l"(reinterpret_cast<u64 const&>(b)),
          "l"(reinterpret_cast<u64 const&>(c)));
    return d;
}
__device__ __forceinline__ float2 fmul2(float2 a, float2 b) {
    float2 d;
    asm("mul.rn.f32x2 %0, %1, %2;"
        : "=l"(reinterpret_cast<u64&>(d))
        : "l"(reinterpret_cast<u64 const&>(a)),
          "l"(reinterpret_cast<u64 const&>(b)));
    return d;
}
__device__ __forceinline__ float2 fadd2(float2 a, float2 b) {
    float2 d;
    asm("add.rn.f32x2 %0, %1, %2;"
        : "=l"(reinterpret_cast<u64&>(d))
        : "l"(reinterpret_cast<u64 const&>(a)),
          "l"(reinterpret_cast<u64 const&>(b)));
    return d;
}
__device__ __forceinline__ float ex2f(float a) {
    float r; asm("ex2.approx.ftz.f32 %0, %1;" : "=f"(r) : "f"(a)); return r;
}
__device__ __forceinline__ float lg2f(float a) {
    float r; asm("lg2.approx.ftz.f32 %0, %1;" : "=f"(r) : "f"(a)); return r;
}

// ---------------- LayerNorm pre-kernel: warp per token ----------------
__global__ void ln_kernel(const float* __restrict__ x,
                          const float* __restrict__ gamma,
                          const float* __restrict__ beta) {
    int gwarp = (blockIdx.x * blockDim.x + threadIdx.x) >> 5;
    int lane = threadIdx.x & 31;
    float4 v = ((const float4*)(x + (size_t)gwarp * DIM))[lane];
    float s = (v.x + v.y) + (v.z + v.w);
    #pragma unroll
    for (int off = 16; off; off >>= 1) s += __shfl_xor_sync(~0u, s, off);
    float mu = s * (1.0f / DIM);
    float dx = v.x - mu, dy = v.y - mu, dz = v.z - mu, dw = v.w - mu;
    float q = (dx * dx + dy * dy) + (dz * dz + dw * dw);
    #pragma unroll
    for (int off = 16; off; off >>= 1) q += __shfl_xor_sync(~0u, q, off);
    float ve = q * (1.0f / DIM) + 1e-5f;
    float r = rsqrtf(ve);
    float4 g = ((const float4*)gamma)[lane];
    float4 b = ((const float4*)beta)[lane];
    float4 o;
    o.x = fmaf(dx * r, g.x, b.x);
    o.y = fmaf(dy * r, g.y, b.y);
    o.z = fmaf(dz * r, g.z, b.z);
    o.w = fmaf(dw * r, g.w, b.w);
    ((float4*)g_xnorm)[(size_t)gwarp * (DIM / 4) + lane] = o;
    if (lane == 0) g_musv[gwarp] = make_float2(mu, ve * r);  // (mu, sqrt(var+eps))
}

// ---------------- Main kernel: warp-per-o, params in registers ----------------
// wavelet: m = H + a*(xn + T)^2, term = CP*m*2^m
//   a = -H/s^2, T = -t, CP = -0.7292728*ww, H = 0.5*log2(e)
// base: b = sv*(sum xn*W' - K1) + mu*K2,  W'=bw/gamma, K1=sum beta*W', K2=sum bw
__global__ __launch_bounds__(THREADS, 4)
void wave_main(const float* __restrict__ scale,
               const float* __restrict__ trans,
               const float* __restrict__ ww,
               const float* __restrict__ bw,
               const float* __restrict__ gamma,
               const float* __restrict__ beta,
               float* __restrict__ out) {
    const int lane = threadIdx.x & 31;
    const int wid = threadIdx.x >> 5;
    const int o = blockIdx.y * 8 + wid;
    const int j16 = lane & 15;
    const int half = lane >> 4;
    const int dbase = j16 * 8;
    const float H = 0.72134752f;
    const float2 H2 = make_float2(H, H);

    // ---- load + fold params for this lane's 8 d's ----
    float2 T[4], A[4], CP[4], W[4];
    float k1 = 0.0f, k2 = 0.0f;
    {
        const int gi = o * DIM + dbase;
        float4 sc[2], tr[2], wv[2], bwv[2], gm[2], bt[2];
        sc[0] = ((const float4*)(scale + gi))[0]; sc[1] = ((const float4*)(scale + gi))[1];
        tr[0] = ((const float4*)(trans + gi))[0]; tr[1] = ((const float4*)(trans + gi))[1];
        wv[0] = ((const float4*)(ww + gi))[0];    wv[1] = ((const float4*)(ww + gi))[1];
        bwv[0] = ((const float4*)(bw + gi))[0];   bwv[1] = ((const float4*)(bw + gi))[1];
        gm[0] = ((const float4*)(gamma + dbase))[0]; gm[1] = ((const float4*)(gamma + dbase))[1];
        bt[0] = ((const float4*)(beta + dbase))[0];  bt[1] = ((const float4*)(beta + dbase))[1];
        const float* scp = (const float*)sc;
        const float* trp = (const float*)tr;
        const float* wwp = (const float*)wv;
        const float* bwp = (const float*)bwv;
        const float* gmp = (const float*)gm;
        const float* btp = (const float*)bt;
        #pragma unroll
        for (int e = 0; e < 8; e++) {
            float x = scp[e];
            // softplus = log2(1+2^(x*log2e)) * ln2
            float sp = lg2f(1.0f + ex2f(1.44269504f * x)) * 0.69314718f;
            float s = sp + 0.1f;
            float a = -H / (s * s);
            float wprime = bwp[e] / gmp[e];
            ((float*)T)[e]  = -trp[e];
            ((float*)A)[e]  = a;
            ((float*)CP)[e] = -0.7292728f * wwp[e];
            ((float*)W)[e]  = wprime;
            k1 += wprime * btp[e];
            k2 += bwp[e];
        }
    }
    // reduce K1,K2 over the 16-lane half (both halves identical params)
    #pragma unroll
    for (int off = 8; off; off >>= 1) {
        k1 += __shfl_xor_sync(~0u, k1, off);
        k2 += __shfl_xor_sync(~0u, k2, off);
    }

    const float* xn_base = g_xnorm + ((size_t)blockIdx.x * TOKB + half) * DIM + dbase;
    float* out_base = out + ((size_t)blockIdx.x * TOKB + half) * ODIM + o;

    #pragma unroll 1
    for (int batch = 0; batch < TOKB / 16; batch++) {
        float swS = 0.0f, sbS = 0.0f;
        #pragma unroll
        for (int k = 0; k < 8; k++) {
            const float* xp = xn_base + ((size_t)batch * 16 + 2 * k) * DIM;
            float4 x0 = ((const float4*)xp)[0];
            float4 x1 = ((const float4*)xp)[1];
            float2 xnp[4];
            xnp[0] = make_float2(x0.x, x0.y);
            xnp[1] = make_float2(x0.z, x0.w);
            xnp[2] = make_float2(x1.x, x1.y);
            xnp[3] = make_float2(x1.z, x1.w);
            float2 accw = make_float2(0.0f, 0.0f);
            float2 accb = make_float2(0.0f, 0.0f);
            #pragma unroll
            for (int p = 0; p < 4; p++) {
                float2 y = fadd2(xnp[p], T[p]);
                float2 q = fmul2(y, y);
                float2 m = ffma2(q, A[p], H2);
                float2 e = make_float2(ex2f(m.x), ex2f(m.y));
                float2 t = fmul2(m, e);
                accw = ffma2(t, CP[p], accw);
                accb = ffma2(xnp[p], W[p], accb);
            }
            float sw = accw.x + accw.y;
            float sb = accb.x + accb.y;
            #pragma unroll
            for (int off = 8; off; off >>= 1) {
                sw += __shfl_xor_sync(~0u, sw, off);
                sb += __shfl_xor_sync(~0u, sb, off);
            }
            // predicated capture: lane j16==k keeps this iteration's sums
            swS = (j16 == k) ? sw : swS;
            sbS = (j16 == k) ? sb : sbS;
        }
        // batched epilogue: 16 lanes (j16<8 in each half) -> 16 tokens per MUFU instr
        if (j16 < 8) {
            int trel = batch * 16 + 2 * j16;
            float2 ms = g_musv[blockIdx.x * TOKB + half + trel];
            float b = fmaf(ms.y, sbS - k1, ms.x * k2);
            float t = ex2f(-1.44269504f * b);
            float sig = __frcp_rn(1.0f + t);
            out_base[(size_t)trel * ODIM] = fmaf(b, sig, swS);
        }
    }
}

extern "C" void kernel_launch(void* const* d_in, const int* in_sizes, int n_in,
                              void* d_out, int out_size) {
    const float* x     = (const float*)d_in[0];
    const float* scale = (const float*)d_in[1];
    const float* trans = (const float*)d_in[2];
    const float* ww    = (const float*)d_in[3];
    const float* bw    = (const float*)d_in[4];
    const float* gamma = (const float*)d_in[5];
    const float* beta  = (const float*)d_in[6];
    float* out = (float*)d_out;

    ln_kernel<<<NTOK / 8, 256>>>(x, gamma, beta);
    dim3 grid(NTOK / TOKB, ODIM / 8);
    wave_main<<<grid, THREADS>>>(scale, trans, ww, bw, gamma, beta, out);
}